// round 4
// baseline (speedup 1.0000x reference)
#include <cuda_runtime.h>
#include <cuda_bf16.h>
#include <cstdint>

// Problem constants
#define BB 2048
#define SS 512
#define DD 128
#define HH 64
#define OO 8
#define H4 16
#define EPSF 1e-5f

typedef unsigned long long u64;

#define DI __device__ __forceinline__

DI u64 pk2(float lo, float hi) {
    u64 r; asm("mov.b64 %0, {%1, %2};" : "=l"(r) : "f"(lo), "f"(hi)); return r;
}
DI void upk2(u64 v, float& lo, float& hi) {
    asm("mov.b64 {%0, %1}, %2;" : "=f"(lo), "=f"(hi) : "l"(v));
}
DI u64 ffma2(u64 a, u64 b, u64 c) {
    u64 d; asm("fma.rn.f32x2 %0, %1, %2, %3;" : "=l"(d) : "l"(a), "l"(b), "l"(c)); return d;
}

// ---- device scratch (static; runtime alloc is forbidden) ----
__device__ float g_xp[(size_t)SS * BB * HH];   // 256 MB: xp[s][b][h]
__device__ float g_z1[BB * H4];
__device__ float g_bn1a[HH], g_bn1c[HH];
__device__ float g_part[16][2][H4];
__device__ float g_bn2a[H4], g_bn2c[H4];

// =====================================================================
// K1: xp[s][b][i] = sum_d x[b][s][d] * W_ih[i][d] + b_ih[i] + b_hh[i]
// Warp task = (row, feature-half). Lane owns one output feature:
// W_ih row (128 floats) in registers as 64 f32x2 pairs; x row broadcast
// from SMEM via LDS.64.
// =====================================================================
__global__ void __launch_bounds__(128, 3) k_proj(
    const float* __restrict__ x, const float* __restrict__ Wih,
    const float* __restrict__ bih, const float* __restrict__ bhh)
{
    __shared__ __align__(16) float sx[4][DD];
    const int lane = threadIdx.x & 31;
    const int warp = threadIdx.x >> 5;
    const int gw   = blockIdx.x * 4 + warp;
    const int NW   = gridDim.x * 4;
    const int half = gw & 1;
    const int i    = half * 32 + lane;

    // load my W_ih row into registers (packed pairs along d)
    u64 w[64];
    const float2* wp = (const float2*)(Wih + (size_t)i * DD);
#pragma unroll
    for (int k = 0; k < 64; k++) { float2 t = wp[k]; w[k] = pk2(t.x, t.y); }
    const float bias = bih[i] + bhh[i];

    const unsigned RSTR  = (unsigned)(NW >> 1);
    const unsigned NROWS = (unsigned)BB * (unsigned)SS;
    unsigned r = (unsigned)(gw >> 1);
    if (r >= NROWS) return;

    // prefetch first x row
    float4 xv = ((const float4*)(x + (size_t)r * DD))[lane];

    for (; r < NROWS; r += RSTR) {
        // stage current row to smem
        *(float4*)&sx[warp][lane * 4] = xv;
        __syncwarp();
        // prefetch next row
        unsigned rn = r + RSTR;
        if (rn < NROWS) xv = ((const float4*)(x + (size_t)rn * DD))[lane];

        u64 a0 = 0, a1 = 0, a2 = 0, a3 = 0;
        const u64* sxp = (const u64*)sx[warp];
#pragma unroll
        for (int k = 0; k < 64; k += 4) {
            a0 = ffma2(w[k],     sxp[k],     a0);
            a1 = ffma2(w[k + 1], sxp[k + 1], a1);
            a2 = ffma2(w[k + 2], sxp[k + 2], a2);
            a3 = ffma2(w[k + 3], sxp[k + 3], a3);
        }
        __syncwarp();

        float l0, h0, l1, h1, l2, h2, l3, h3;
        upk2(a0, l0, h0); upk2(a1, l1, h1); upk2(a2, l2, h2); upk2(a3, l3, h3);
        float v = ((l0 + h0) + (l1 + h1)) + ((l2 + h2) + (l3 + h3)) + bias;

        unsigned b = r >> 9;          // r / SS  (SS = 512)
        unsigned s = r & (SS - 1);    // r % SS
        g_xp[((size_t)s * BB + b) * HH + i] = v;
    }
}

// =====================================================================
// K2: recurrence. Warp owns 2 batch rows; lane owns outputs (lane, lane+32)
// for both rows. W_hh rows in registers (64 f32x2). h double-buffered in
// SMEM, broadcast via LDS.64. One __syncwarp per step. 512 serial steps.
// =====================================================================
__global__ void __launch_bounds__(128, 2) k_rnn(
    const float* __restrict__ h0, const float* __restrict__ Whh,
    float* __restrict__ dout)
{
    __shared__ __align__(16) float sh[4][2][2][HH];  // [warp][row][buf][64]
    const int lane = threadIdx.x & 31;
    const int warp = threadIdx.x >> 5;
    const int gw   = blockIdx.x * 4 + warp;          // 0..1023
    const int b0   = gw * 2;
    const int b1   = gw * 2 + 1;

    // W_hh rows lane and lane+32, packed pairs along j
    u64 w0[32], w1[32];
    const float2* p0 = (const float2*)(Whh + (size_t)lane * HH);
    const float2* p1 = (const float2*)(Whh + (size_t)(lane + 32) * HH);
#pragma unroll
    for (int k = 0; k < 32; k++) {
        float2 t = p0[k]; w0[k] = pk2(t.x, t.y);
        float2 u = p1[k]; w1[k] = pk2(u.x, u.y);
    }

    float (*shw)[2][HH] = sh[warp];
    // init h from h0
    shw[0][0][lane]      = h0[(size_t)b0 * HH + lane];
    shw[0][0][lane + 32] = h0[(size_t)b0 * HH + lane + 32];
    shw[1][0][lane]      = h0[(size_t)b1 * HH + lane];
    shw[1][0][lane + 32] = h0[(size_t)b1 * HH + lane + 32];
    __syncwarp();

    // prefetch xp for s=0
    float px00 = g_xp[((size_t)0 * BB + b0) * HH + lane];
    float px01 = g_xp[((size_t)0 * BB + b0) * HH + lane + 32];
    float px10 = g_xp[((size_t)0 * BB + b1) * HH + lane];
    float px11 = g_xp[((size_t)0 * BB + b1) * HH + lane + 32];

    int buf = 0;
    float v00 = 0.f, v01 = 0.f, v10 = 0.f, v11 = 0.f;

    for (int s = 0; s < SS; s++) {
        // prefetch next step's xp
        float n00 = 0.f, n01 = 0.f, n10 = 0.f, n11 = 0.f;
        if (s + 1 < SS) {
            size_t base = (size_t)(s + 1) * BB;
            n00 = g_xp[(base + b0) * HH + lane];
            n01 = g_xp[(base + b0) * HH + lane + 32];
            n10 = g_xp[(base + b1) * HH + lane];
            n11 = g_xp[(base + b1) * HH + lane + 32];
        }

        u64 a00 = 0, a01 = 0, a10 = 0, a11 = 0;
        const u64* hp0 = (const u64*)shw[0][buf];
        const u64* hp1 = (const u64*)shw[1][buf];
#pragma unroll
        for (int k = 0; k < 32; k++) {
            u64 h0p = hp0[k];
            u64 h1p = hp1[k];
            a00 = ffma2(w0[k], h0p, a00);
            a01 = ffma2(w1[k], h0p, a01);
            a10 = ffma2(w0[k], h1p, a10);
            a11 = ffma2(w1[k], h1p, a11);
        }

        float lo, hi;
        upk2(a00, lo, hi); v00 = fmaxf(lo + hi + px00, 0.f);
        upk2(a01, lo, hi); v01 = fmaxf(lo + hi + px01, 0.f);
        upk2(a10, lo, hi); v10 = fmaxf(lo + hi + px10, 0.f);
        upk2(a11, lo, hi); v11 = fmaxf(lo + hi + px11, 0.f);

        buf ^= 1;
        shw[0][buf][lane]      = v00;
        shw[0][buf][lane + 32] = v01;
        shw[1][buf][lane]      = v10;
        shw[1][buf][lane + 32] = v11;
        __syncwarp();

        px00 = n00; px01 = n01; px10 = n10; px11 = n11;
    }

    // hidden output lives after out[B,O] in d_out
    float* hT = dout + (size_t)BB * OO;
    hT[(size_t)b0 * HH + lane]      = v00;
    hT[(size_t)b0 * HH + lane + 32] = v01;
    hT[(size_t)b1 * HH + lane]      = v10;
    hT[(size_t)b1 * HH + lane + 32] = v11;
}

// =====================================================================
// K3: batchnorm-1 stats. One block per feature.
// =====================================================================
__global__ void k_bn1stats(const float* __restrict__ dout,
                           const float* __restrict__ g, const float* __restrict__ bb)
{
    const float* hT = dout + (size_t)BB * OO;
    int f = blockIdx.x, t = threadIdx.x;
    float s = 0.f, q = 0.f;
    for (int b = t; b < BB; b += 256) {
        float v = hT[(size_t)b * HH + f];
        s += v; q += v * v;
    }
    __shared__ float rs[256], rq[256];
    rs[t] = s; rq[t] = q; __syncthreads();
    for (int off = 128; off > 0; off >>= 1) {
        if (t < off) { rs[t] += rs[t + off]; rq[t] += rq[t + off]; }
        __syncthreads();
    }
    if (t == 0) {
        float mu  = rs[0] * (1.f / BB);
        float var = rq[0] * (1.f / BB) - mu * mu;
        float a   = g[f] * rsqrtf(var + EPSF);
        g_bn1a[f] = a;
        g_bn1c[f] = bb[f] - mu * a;
    }
}

// =====================================================================
// K4: z1 = relu(bn1(hT) @ fc1_W^T + b) ; per-block partial bn2 stats.
// grid 16 x 128 (thread = batch row)
// =====================================================================
__global__ void k_fc1(const float* __restrict__ dout,
                      const float* __restrict__ W1, const float* __restrict__ b1f)
{
    const float* hT = dout + (size_t)BB * OO;
    __shared__ float sW[H4 * HH];
    __shared__ float sa[HH], sc[HH], sb[H4];
    __shared__ float red[128];
    int t = threadIdx.x;
    for (int i = t; i < H4 * HH; i += 128) sW[i] = W1[i];
    if (t < HH) { sa[t] = g_bn1a[t]; sc[t] = g_bn1c[t]; }
    if (t < H4) sb[t] = b1f[t];
    __syncthreads();

    int b = blockIdx.x * 128 + t;
    float y[HH];
#pragma unroll
    for (int f = 0; f < HH; f++) y[f] = sa[f] * hT[(size_t)b * HH + f] + sc[f];

    float s[H4], q[H4];
#pragma unroll
    for (int j = 0; j < H4; j++) {
        float acc = sb[j];
#pragma unroll
        for (int f = 0; f < HH; f++) acc += sW[j * HH + f] * y[f];
        acc = fmaxf(acc, 0.f);
        g_z1[(size_t)b * H4 + j] = acc;
        s[j] = acc; q[j] = acc * acc;
    }
    // block reductions (deterministic)
    for (int j = 0; j < H4; j++) {
        red[t] = s[j]; __syncthreads();
        for (int off = 64; off > 0; off >>= 1) {
            if (t < off) red[t] += red[t + off];
            __syncthreads();
        }
        if (t == 0) g_part[blockIdx.x][0][j] = red[0];
        __syncthreads();
        red[t] = q[j]; __syncthreads();
        for (int off = 64; off > 0; off >>= 1) {
            if (t < off) red[t] += red[t + off];
            __syncthreads();
        }
        if (t == 0) g_part[blockIdx.x][1][j] = red[0];
        __syncthreads();
    }
}

// K5: finalize bn2 coefficients
__global__ void k_bn2(const float* __restrict__ g2, const float* __restrict__ b2)
{
    int j = threadIdx.x;
    if (j >= H4) return;
    float s = 0.f, q = 0.f;
    for (int k = 0; k < 16; k++) { s += g_part[k][0][j]; q += g_part[k][1][j]; }
    float mu  = s * (1.f / BB);
    float var = q * (1.f / BB) - mu * mu;
    float a   = g2[j] * rsqrtf(var + EPSF);
    g_bn2a[j] = a;
    g_bn2c[j] = b2[j] - mu * a;
}

// K6: out = bn2(z1) @ fc2_W^T + b.  grid 16 x 128
__global__ void k_fc2(const float* __restrict__ W2, const float* __restrict__ b2f,
                      float* __restrict__ out)
{
    __shared__ float sW[OO * H4], sa[H4], sc[H4], sb[OO];
    int t = threadIdx.x;
    if (t < OO * H4) sW[t] = W2[t];
    if (t < H4) { sa[t] = g_bn2a[t]; sc[t] = g_bn2c[t]; }
    if (t < OO) sb[t] = b2f[t];
    __syncthreads();

    int b = blockIdx.x * 128 + t;
    float z[H4];
#pragma unroll
    for (int j = 0; j < H4; j++) z[j] = sa[j] * g_z1[(size_t)b * H4 + j] + sc[j];
#pragma unroll
    for (int o = 0; o < OO; o++) {
        float acc = sb[o];
#pragma unroll
        for (int j = 0; j < H4; j++) acc += sW[o * H4 + j] * z[j];
        out[(size_t)b * OO + o] = acc;
    }
}

// =====================================================================
extern "C" void kernel_launch(void* const* d_in, const int* in_sizes, int n_in,
                              void* d_out, int out_size)
{
    const float* x    = (const float*)d_in[0];
    const float* h0   = (const float*)d_in[1];
    const float* Wih  = (const float*)d_in[2];
    const float* Whh  = (const float*)d_in[3];
    const float* bih  = (const float*)d_in[4];
    const float* bhh  = (const float*)d_in[5];
    const float* bn1g = (const float*)d_in[6];
    const float* bn1b = (const float*)d_in[7];
    const float* fc1W = (const float*)d_in[8];
    const float* fc1b = (const float*)d_in[9];
    const float* bn2g = (const float*)d_in[10];
    const float* bn2b = (const float*)d_in[11];
    const float* fc2W = (const float*)d_in[12];
    const float* fc2b = (const float*)d_in[13];
    float* out = (float*)d_out;

    cudaStream_t s0 = 0;
    k_proj<<<444, 128, 0, s0>>>(x, Wih, bih, bhh);
    k_rnn<<<256, 128, 0, s0>>>(h0, Whh, out);
    k_bn1stats<<<64, 256, 0, s0>>>(out, bn1g, bn1b);
    k_fc1<<<16, 128, 0, s0>>>(out, fc1W, fc1b);
    k_bn2<<<1, 32, 0, s0>>>(bn2g, bn2b);
    k_fc2<<<16, 128, 0, s0>>>(fc2W, fc2b, out);
}